// round 3
// baseline (speedup 1.0000x reference)
#include <cuda_runtime.h>
#include <cstdint>

#define NBINS   36
#define HIDDEN  128
#define MAXN    8192
#define THREADS 256
#define JCHUNK  512

// Scratch occupancy counts (integer; weights are 0/1). Zeroed every launch.
__device__ int g_occ[MAXN * NBINS];

__global__ void zero_occ(int n4) {
    int idx = blockIdx.x * blockDim.x + threadIdx.x;
    int4* p = (int4*)g_occ;
    if (idx < n4) p[idx] = make_int4(0, 0, 0, 0);
}

// Block: 256 agents (one per thread) x one 512-j chunk.
// Per-thread private histogram in SMEM, layout [bin][tid] -> bank-conflict-free.
__global__ __launch_bounds__(THREADS) void hist_kernel(const float2* __restrict__ obs, int N) {
    __shared__ int    hist[NBINS * THREADS];   // 36 KB
    __shared__ float2 jt[JCHUNK];              // 4 KB

    const int tid = threadIdx.x;
    const int i   = blockIdx.x * THREADS + tid;
    const int j0  = blockIdx.y * JCHUNK;

    float2 pi = (i < N) ? obs[i] : make_float2(0.f, 0.f);
    const bool ivalid = (i < N) && (pi.x == pi.x) && (pi.y == pi.y);
    float nx = -pi.x, ny = -pi.y;
    if (!ivalid) { nx = -1e38f; ny = -1e38f; }   // forces rel out of range (INT_MIN)

    unsigned long long nxi, two2, three3;
    asm("mov.b64 %0, {%1, %2};" : "=l"(nxi)    : "f"(nx),   "f"(ny));
    asm("mov.b64 %0, {%1, %2};" : "=l"(two2)   : "f"(2.0f), "f"(2.0f));
    asm("mov.b64 %0, {%1, %2};" : "=l"(three3) : "f"(3.0f), "f"(3.0f));

    #pragma unroll
    for (int k = 0; k < NBINS; k++) hist[k * THREADS + tid] = 0;

    // Stage j tile; NaN / OOB j replaced by +3e38 -> rel saturates to INT_MAX (invalid).
    // Asymmetric magnitudes (1e38 vs 3e38) keep NaN-i + NaN-j pairs invalid too.
    for (int s = tid; s < JCHUNK; s += THREADS) {
        int j = j0 + s;
        float2 p = (j < N) ? obs[j] : make_float2(3e38f, 3e38f);
        if (!(p.x == p.x) || !(p.y == p.y)) { p.x = 3e38f; p.y = 3e38f; }
        jt[s] = p;
    }
    __syncthreads();

    const unsigned long long* jt64 = (const unsigned long long*)jt;
    int* hrow = hist + tid;

    #pragma unroll 8
    for (int s = 0; s < JCHUNK; s++) {
        unsigned long long p = jt64[s];          // LDS.64, broadcast across warp
        unsigned long long d, r;
        // d = p - pi  (lanewise RN, matches reference's subtract rounding)
        asm("add.rn.f32x2 %0, %1, %2;" : "=l"(d) : "l"(p), "l"(nxi));
        // r = 2*d + 3 (2*d exact, single RN == reference's (d/0.5)+3 rounding)
        asm("fma.rn.f32x2 %0, %1, %2, %3;" : "=l"(r) : "l"(d), "l"(two2), "l"(three3));
        float rx = __uint_as_float((unsigned)(r & 0xffffffffull));
        float ry = __uint_as_float((unsigned)(r >> 32));
        int ix = __float2int_rd(rx);             // floor; saturates on +-inf/huge
        int iy = __float2int_rd(ry);
        if ((unsigned)ix < 6u && (unsigned)iy < 6u)
            hrow[(ix * 6 + iy) * THREADS]++;
    }

    // Self-pair lands exactly at rel=(3,3) -> cell 21; remove once.
    if (ivalid && i >= j0 && i < j0 + JCHUNK) hrow[21 * THREADS]--;

    if (i < N) {
        #pragma unroll
        for (int b = 0; b < NBINS; b++) {
            int c = hrow[b * THREADS];
            if (c) atomicAdd(&g_occ[i * NBINS + b], c);
        }
    }
}

// out[i][h] = b[h] + sum_k occ[i][k] * W[h][k].  W row kept in registers,
// occ tile staged to SMEM (broadcast reads).
__global__ __launch_bounds__(HIDDEN) void gemm_kernel(const float* __restrict__ W,
                                                      const float* __restrict__ bias,
                                                      float* __restrict__ out, int N) {
    const int RPB = 16;
    __shared__ float occ_s[RPB * NBINS];
    const int h  = threadIdx.x;
    const int i0 = blockIdx.x * RPB;

    float w[NBINS];
    #pragma unroll
    for (int k = 0; k < NBINS; k++) w[k] = W[h * NBINS + k];
    const float bh = bias[h];

    for (int t = h; t < RPB * NBINS; t += HIDDEN) {
        int row = i0 + t / NBINS;
        occ_s[t] = (row < N) ? (float)g_occ[i0 * NBINS + t] : 0.f;
    }
    __syncthreads();

    #pragma unroll
    for (int r = 0; r < RPB; r++) {
        int i = i0 + r;
        if (i >= N) break;
        float acc = bh;
        #pragma unroll
        for (int k = 0; k < NBINS; k++) acc += occ_s[r * NBINS + k] * w[k];
        out[i * HIDDEN + h] = acc;
    }
}

extern "C" void kernel_launch(void* const* d_in, const int* in_sizes, int n_in,
                              void* d_out, int out_size) {
    const float2* obs  = (const float2*)d_in[0];
    const float*  W    = (const float*)d_in[1];
    const float*  bias = (const float*)d_in[2];
    float* out = (float*)d_out;
    const int N = in_sizes[0] / 2;

    int n4 = (N * NBINS + 3) / 4;
    zero_occ<<<(n4 + 255) / 256, 256>>>(n4);

    dim3 hg((N + THREADS - 1) / THREADS, (N + JCHUNK - 1) / JCHUNK);
    hist_kernel<<<hg, THREADS>>>(obs, N);

    gemm_kernel<<<(N + 15) / 16, HIDDEN>>>(W, bias, out, N);
}

// round 5
// speedup vs baseline: 1.3052x; 1.3052x over previous
#include <cuda_runtime.h>
#include <cstdint>

#define NBINS   36
#define HIDDEN  128
#define THREADS 256
#define ITILE   16      // agents per block
#define LANES   16      // j-lanes per agent
#define JCHUNK  512     // j per staged chunk

// One fused kernel: block = 16 agents x ALL j. Per-thread private SMEM hist
// (layout [bin][tid] -> bank tid%32, conflict-free). No global scratch,
// no atomics, linear layer fused as epilogue.
__global__ __launch_bounds__(THREADS, 4)
void occ_fused_kernel(const float2* __restrict__ obs,
                      const float*  __restrict__ W,
                      const float*  __restrict__ bias,
                      float* __restrict__ out, int N) {
    __shared__ int hist[NBINS * THREADS];                          // 36 KB
    __shared__ __align__(16) unsigned long long jt[2][JCHUNK];     // 8 KB (2 x 512 packed points)

    const int tid  = threadIdx.x;
    const int lane = tid & (LANES - 1);
    const int il   = tid >> 4;
    const int i0   = blockIdx.x * ITILE;
    const int i    = i0 + il;

    float2 pi = (i < N) ? obs[i] : make_float2(0.f, 0.f);
    const bool ivalid = (i < N) && (pi.x == pi.x) && (pi.y == pi.y);
    float nx = ivalid ? -pi.x : -1e38f;    // invalid i -> r huge-negative -> rejected
    float ny = ivalid ? -pi.y : -1e38f;

    unsigned long long nxi, two2, three3;
    asm("mov.b64 %0, {%1, %2};" : "=l"(nxi)    : "f"(nx),   "f"(ny));
    asm("mov.b64 %0, {%1, %2};" : "=l"(two2)   : "f"(2.0f), "f"(2.0f));
    asm("mov.b64 %0, {%1, %2};" : "=l"(three3) : "f"(3.0f), "f"(3.0f));

    #pragma unroll
    for (int k = 0; k < NBINS; k++) hist[k * THREADS + tid] = 0;

    const int nchunk = (N + JCHUNK - 1) / JCHUNK;

    // Stage one chunk (2 points per thread). NaN/OOB j -> +3e38 (rejected;
    // asymmetric vs -1e38 on i so invalid+invalid pairs stay invalid).
    auto stage = [&](int c, int buf) {
        int j = c * JCHUNK + tid * 2;
        float4 v;
        if (j + 1 < N)      v = *(const float4*)(&obs[j]);
        else if (j < N)   { float2 t = obs[j]; v = make_float4(t.x, t.y, 3e38f, 3e38f); }
        else                v = make_float4(3e38f, 3e38f, 3e38f, 3e38f);
        if (!(v.x == v.x) || !(v.y == v.y)) { v.x = 3e38f; v.y = 3e38f; }
        if (!(v.z == v.z) || !(v.w == v.w)) { v.z = 3e38f; v.w = 3e38f; }
        unsigned long long p0, p1;
        asm("mov.b64 %0, {%1, %2};" : "=l"(p0) : "f"(v.x), "f"(v.y));
        asm("mov.b64 %0, {%1, %2};" : "=l"(p1) : "f"(v.z), "f"(v.w));
        *(ulonglong2*)&jt[buf][2 * tid] = make_ulonglong2(p0, p1);
    };

    int* const hrow = hist + tid;

    // Per-point: d = RN(p - pi); r = RN(2d + 3)  [bit-exact vs reference];
    // floor via FADD.RZ magic: bits(rz(r + 2^23)) = 0x4B000000 + floor(r) for r >= 0.
    // Negative / inf / NaN-sourced r all fail the unsigned < 6 checks.
#define PROC_PT(P) do {                                                         \
        unsigned long long d_, r_;                                              \
        asm("add.rn.f32x2 %0, %1, %2;" : "=l"(d_) : "l"(P), "l"(nxi));          \
        asm("fma.rn.f32x2 %0, %1, %2, %3;"                                      \
            : "=l"(r_) : "l"(d_), "l"(two2), "l"(three3));                      \
        float rx_, ry_;                                                         \
        asm("mov.b64 {%0, %1}, %2;" : "=f"(rx_), "=f"(ry_) : "l"(r_));          \
        int tx_ = __float_as_int(__fadd_rz(rx_, 8388608.0f)) - 0x4B000000;      \
        int ty_ = __float_as_int(__fadd_rz(ry_, 8388608.0f)) - 0x4B000000;      \
        if ((unsigned)tx_ < 6u && (unsigned)ty_ < 6u)                           \
            hrow[(tx_ * 6 + ty_) << 8]++;                                       \
    } while (0)

    int buf = 0;
    stage(0, 0);
    __syncthreads();
    for (int c = 0; c < nchunk; c++) {
        if (c + 1 < nchunk) stage(c + 1, buf ^ 1);
        const unsigned long long* jb = jt[buf];
        // Interleaved lane assignment: lane l, iter u -> point pair u*16 + l.
        // LDS.128 per pair: 16 unique 16B addrs, 16B stride -> 2 wavefronts (optimal).
        #pragma unroll 4
        for (int u = 0; u < JCHUNK / (2 * LANES); u++) {
            ulonglong2 e = *(const ulonglong2*)&jb[2 * (u * LANES + lane)];
            PROC_PT(e.x);
            PROC_PT(e.y);
        }
        __syncthreads();
        buf ^= 1;
    }

    // Remove self-pair: lands exactly at r=(3,3) -> bin 21, counted by the lane
    // that owns point j==i within its chunk.
    if (tid < ITILE) {
        int ii = i0 + tid;
        if (ii < N) {
            float2 p = obs[ii];
            if (p.x == p.x && p.y == p.y) {
                int ln = ((ii & (JCHUNK - 1)) >> 1) & (LANES - 1);
                hist[21 * THREADS + tid * LANES + ln] -= 1;
            }
        }
    }
    __syncthreads();

    // Reduce 16 lane-hists per agent -> occ_s[16][36] (reuses jt storage).
    float* occ_s = (float*)jt;
    for (int idx = tid; idx < ITILE * NBINS; idx += THREADS) {
        int iL = idx / NBINS, b = idx - iL * NBINS;
        const int* hp = hist + b * THREADS + iL * LANES;
        int s = 0;
        #pragma unroll
        for (int l = 0; l < LANES; l++) s += hp[l];
        occ_s[iL * NBINS + b] = (float)s;
    }
    __syncthreads();

    // Fused linear: out[i][h] = b[h] + sum_k occ[i][k] * W[h][k].
    {
        int h  = tid & (HIDDEN - 1);
        int ib = (tid >> 7) * (ITILE / 2);     // 0 or 8
        float w[NBINS];
        #pragma unroll
        for (int k = 0; k < NBINS; k++) w[k] = W[h * NBINS + k];
        float bh = bias[h];
        #pragma unroll
        for (int r = 0; r < ITILE / 2; r++) {
            int iL = ib + r;
            int ii = i0 + iL;
            if (ii >= N) break;
            float acc = bh;
            #pragma unroll
            for (int k = 0; k < NBINS; k++)
                acc = fmaf(occ_s[iL * NBINS + k], w[k], acc);
            out[ii * HIDDEN + h] = acc;
        }
    }
#undef PROC_PT
}

extern "C" void kernel_launch(void* const* d_in, const int* in_sizes, int n_in,
                              void* d_out, int out_size) {
    const float2* obs  = (const float2*)d_in[0];
    const float*  W    = (const float*)d_in[1];
    const float*  bias = (const float*)d_in[2];
    float* out = (float*)d_out;
    const int N = in_sizes[0] / 2;

    int nb = (N + ITILE - 1) / ITILE;
    occ_fused_kernel<<<nb, THREADS>>>(obs, W, bias, out, N);
}